// round 16
// baseline (speedup 1.0000x reference)
#include <cuda_runtime.h>
#include <cuda_fp16.h>
#include <cstdint>

#define DI __device__ __forceinline__

constexpr int D = 128, G = 8, F = 80, A = 18;
constexpr int BM = 128, THREADS = 256;

// strides in 32-bit WORDS (each word = 2 fp16)
constexpr int XSW  = 68;  // X row stride (64 data + 4 pad): bank 4g+t distinct -> conflict-free
constexpr int W1SW = 68;  // W1 full-K slot row stride (64 data + 4 pad): same proof
constexpr int WS   = 44;  // W2/3/4 slot row stride (40 data + 4 pad): 44%32=12 -> distinct
constexpr int SLOTW = F * W1SW;             // 5440 words per slot (max stage = full W1[g])
constexpr int OFF_X  = 0;                   // 128*68 = 8704 words
constexpr int OFF_SL = BM * XSW;            // 3 rotating slots
constexpr int OFF_SB = OFF_SL + 3 * SLOTW;  // biases: b1(640) b2(80) b3(80) b4(144)
constexpr int NBIAS  = G * F + F + F + G * A;   // 944
constexpr int SMEM_WORDS = OFF_SB + NBIAS;  // 25968
constexpr int SMEM_BYTES = SMEM_WORDS * 4;  // 103872 B -> 2 CTAs/SM

// fp16-packed weight images (layout == staged layout; one uint32 = 2 halves)
__device__ __align__(16) uint32_t g_W1h[G * F * W1SW];  // [g][n][68w] full-K
__device__ __align__(16) uint32_t g_W23h[2 * F * WS];   // [l][n][44w]
__device__ __align__(16) uint32_t g_W4h[G * 24 * WS];   // [g][n<24][44w]

DI uint32_t packh2(float a, float b) {
    __half2 h = __floats2half2_rn(a, b);
    return *(uint32_t*)&h;
}

DI void mma16(float* c, uint32_t a0, uint32_t a1, uint32_t a2, uint32_t a3,
              uint32_t b0, uint32_t b1) {
    asm("mma.sync.aligned.m16n8k16.row.col.f32.f16.f16.f32 "
        "{%0,%1,%2,%3}, {%4,%5,%6,%7}, {%8,%9}, {%0,%1,%2,%3};"
        : "+f"(c[0]), "+f"(c[1]), "+f"(c[2]), "+f"(c[3])
        : "r"(a0), "r"(a1), "r"(a2), "r"(a3), "r"(b0), "r"(b1));
}

DI void cpa16(uint32_t dst, const void* src) {
    asm volatile("cp.async.cg.shared.global [%0], [%1], 16;" :: "r"(dst), "l"(src));
}
#define CPA_COMMIT() asm volatile("cp.async.commit_group;" ::: "memory")
#define CPA_WAIT1()  asm volatile("cp.async.wait_group 1;" ::: "memory")

__global__ void prep_kernel(const float* __restrict__ W1, const float* __restrict__ W2,
                            const float* __restrict__ W3, const float* __restrict__ W4) {
    int i = blockIdx.x * blockDim.x + threadIdx.x;
    if (i < G * F * W1SW) {  // i = (g*F + n)*68 + w
        int w = i % W1SW; int r = i / W1SW;
        int n = r % F; int g = r / F;
        uint32_t v = 0;
        if (w < 64) {
            const float* p = W1 + (size_t)(g * F + n) * D + 2 * w;
            v = packh2(p[0], p[1]);
        }
        g_W1h[i] = v;
    }
    if (i < 2 * F * WS) {  // i = (l*F + n)*44 + w
        int w = i % WS; int r = i / WS;
        int n = r % F; int l = r / F;
        uint32_t v = 0;
        if (w < 40) {
            const float* W = l ? W3 : W2;
            v = packh2(W[n * F + 2 * w], W[n * F + 2 * w + 1]);
        }
        g_W23h[i] = v;
    }
    if (i < G * 24 * WS) {  // i = (g*24 + n)*44 + w
        int w = i % WS; int r = i / WS;
        int n = r % 24; int g = r / 24;
        uint32_t v = 0;
        if (n < A && w < 40) {
            const float* p = W4 + (size_t)(g * A + n) * F + 2 * w;
            v = packh2(p[0], p[1]);
        }
        g_W4h[i] = v;
    }
}

// prefetch stage s into slot s%3 (linear copies of preformatted images)
DI void issue_stage(int s, int gLo, int nG, uint32_t slbase, int tid) {
    uint32_t dst = slbase + (uint32_t)(s % 3) * (SLOTW * 4);
    const uint32_t* src; int nch;
    if (s < nG) {                           // full W1[g]: 5440 w = 1360 f4
        src = g_W1h + (size_t)(gLo + s) * F * W1SW; nch = 1360;
    } else {
        int t = s - nG;
        if (t < 2) { src = g_W23h + (size_t)t * F * WS; nch = 880; }   // 80*44 w
        else       { src = g_W4h + (size_t)(gLo + t - 2) * 24 * WS; nch = 264; }
    }
    for (int c = tid; c < nch; c += THREADS)
        cpa16(dst + c * 16, src + c * 4);
}

__global__ __launch_bounds__(THREADS, 2)
void fused_kernel(const float* __restrict__ state, const int* __restrict__ idx,
                  const float* __restrict__ b1, const float* __restrict__ b2,
                  const float* __restrict__ b3, const float* __restrict__ b4,
                  float* __restrict__ out, int nTotal)
{
    extern __shared__ float sm[];
    uint32_t* Xw    = (uint32_t*)sm;      // fp16 state (64 w/row), then h (40 w/row) in place
    float*    sbias = sm + OFF_SB;        // [0..639]=b1, [640..719]=b2, [720..799]=b3, [800..943]=b4

    uint32_t su;
    asm("{ .reg .u64 t; cvta.to.shared.u64 t, %1; cvt.u32.u64 %0, t; }"
        : "=r"(su) : "l"(sm));
    const uint32_t slbase = su + OFF_SL * 4;

    const int tid  = threadIdx.x;
    const int lane = tid & 31;
    const int wid  = tid >> 5;
    const int gid  = lane >> 2;
    const int tig  = lane & 3;

    // 4 m-warps x 2 n-warps; each warp: 2 m16 tiles x 5 n-tiles (its 40 cols)
    const int mw = wid & 3;
    const int nw = wid >> 2;
    const int nbase = nw * 40;            // column base (half units)
    const int nbw   = nw * 20;            // column base (word units)
    const int rA0 = mw * 32 + gid;
    const int rA1 = mw * 32 + 16 + gid;

    const int mBase  = blockIdx.x * BM;
    const int nValid = min(BM, nTotal - mBase);

    const int gLo = __ldg(&idx[mBase]);
    const int gHi = __ldg(&idx[mBase + nValid - 1]);
    const int nG = gHi - gLo + 1;
    const int nStages = 2 * nG + 2;  // nG (W1 full) + 2 (W2,W3) + nG (W4)

    int mg[2][2];
    mg[0][0] = (rA0     < nValid) ? __ldg(&idx[mBase + rA0])     : -1;
    mg[0][1] = (rA0 + 8 < nValid) ? __ldg(&idx[mBase + rA0 + 8]) : -1;
    mg[1][0] = (rA1     < nValid) ? __ldg(&idx[mBase + rA1])     : -1;
    mg[1][1] = (rA1 + 8 < nValid) ? __ldg(&idx[mBase + rA1 + 8]) : -1;

    // ---- prologue ----
    // state: fp32 LDG -> fp16 pack -> STS (coalesced)
    {
        const float4* s4 = (const float4*)state;
        for (int c = tid; c < BM * 32; c += THREADS) {
            int m = c >> 5, c4 = c & 31;
            int row = min(mBase + m, nTotal - 1);
            float4 v = s4[(size_t)row * 32 + c4];
            Xw[m * XSW + 2 * c4]     = packh2(v.x, v.y);
            Xw[m * XSW + 2 * c4 + 1] = packh2(v.z, v.w);
        }
    }
    // biases -> smem (cp.async, rides in group 0)
    {
        const uint32_t sbb = su + OFF_SB * 4;
        if (tid < 160) cpa16(sbb + tid * 16, b1 + tid * 4);                 // 640 floats
        if (tid < 20)  cpa16(sbb + 640 * 4 + tid * 16, b2 + tid * 4);       // 80
        if (tid < 20)  cpa16(sbb + 720 * 4 + tid * 16, b3 + tid * 4);       // 80
        if (tid < 36)  cpa16(sbb + 800 * 4 + tid * 16, b4 + tid * 4);       // 144
    }
    issue_stage(0, gLo, nG, slbase, tid); CPA_COMMIT();
    issue_stage(1, gLo, nG, slbase, tid); CPA_COMMIT();

    float acc[2][5][4];

    for (int s = 0; s < nStages; ++s) {
        CPA_WAIT1();
        __syncthreads();  // stage s weights (+ at s=0: state tile & biases) visible to all
        const uint32_t* SWw = (const uint32_t*)sm + OFF_SL + (s % 3) * SLOTW;

        if (s < nG) {
            // ---------- Layer 1, FULL K, game g (8 k16-steps) ----------
            int g = gLo + s;
            #pragma unroll
            for (int t = 0; t < 2; ++t)
                #pragma unroll
                for (int nt = 0; nt < 5; ++nt)
                    #pragma unroll
                    for (int i = 0; i < 4; ++i) acc[t][nt][i] = 0.f;
            #pragma unroll
            for (int ks = 0; ks < 8; ++ks) {
                int kx = ks * 8;   // word offset into state
                uint32_t af[2][4];
                af[0][0] = Xw[rA0 * XSW + kx + tig];
                af[0][1] = Xw[(rA0 + 8) * XSW + kx + tig];
                af[0][2] = Xw[rA0 * XSW + kx + 4 + tig];
                af[0][3] = Xw[(rA0 + 8) * XSW + kx + 4 + tig];
                af[1][0] = Xw[rA1 * XSW + kx + tig];
                af[1][1] = Xw[(rA1 + 8) * XSW + kx + tig];
                af[1][2] = Xw[rA1 * XSW + kx + 4 + tig];
                af[1][3] = Xw[(rA1 + 8) * XSW + kx + 4 + tig];
                #pragma unroll
                for (int nt = 0; nt < 5; ++nt) {
                    const uint32_t* bp = SWw + (nbase + nt * 8 + gid) * W1SW + kx + tig;
                    uint32_t b0 = bp[0], b1v = bp[4];
                    mma16(acc[0][nt], af[0][0], af[0][1], af[0][2], af[0][3], b0, b1v);
                    mma16(acc[1][nt], af[1][0], af[1][1], af[1][2], af[1][3], b0, b1v);
                }
            }
            // h1 overwrites state words 0..39 which this stage's MMAs read:
            // wait for ALL warps' reads before anyone writes.
            __syncthreads();
            #pragma unroll
            for (int t = 0; t < 2; ++t) {
                int rr = (t == 0) ? rA0 : rA1;
                #pragma unroll
                for (int hf = 0; hf < 2; ++hf) {
                    if (mg[t][hf] == g) {
                        int row = rr + hf * 8;
                        #pragma unroll
                        for (int nt = 0; nt < 5; ++nt) {
                            int c = nbase + nt * 8 + 2 * tig;
                            float v0 = fmaxf(acc[t][nt][2 * hf]     + sbias[g * F + c],     0.f);
                            float v1 = fmaxf(acc[t][nt][2 * hf + 1] + sbias[g * F + c + 1], 0.f);
                            Xw[row * XSW + nbw + nt * 4 + tig] = packh2(v0, v1);
                        }
                    }
                }
            }
        } else if (s - nG < 2) {
            // ---------- Layer 2 or 3, full K (5 k16-steps) ----------
            int l = s - nG;
            #pragma unroll
            for (int t = 0; t < 2; ++t)
                #pragma unroll
                for (int nt = 0; nt < 5; ++nt)
                    #pragma unroll
                    for (int i = 0; i < 4; ++i) acc[t][nt][i] = 0.f;
            #pragma unroll
            for (int ks = 0; ks < 5; ++ks) {
                int kx = ks * 8;
                uint32_t af[2][4];
                af[0][0] = Xw[rA0 * XSW + kx + tig];
                af[0][1] = Xw[(rA0 + 8) * XSW + kx + tig];
                af[0][2] = Xw[rA0 * XSW + kx + 4 + tig];
                af[0][3] = Xw[(rA0 + 8) * XSW + kx + 4 + tig];
                af[1][0] = Xw[rA1 * XSW + kx + tig];
                af[1][1] = Xw[(rA1 + 8) * XSW + kx + tig];
                af[1][2] = Xw[rA1 * XSW + kx + 4 + tig];
                af[1][3] = Xw[(rA1 + 8) * XSW + kx + 4 + tig];
                #pragma unroll
                for (int nt = 0; nt < 5; ++nt) {
                    const uint32_t* bp = SWw + (nbase + nt * 8 + gid) * WS + kx + tig;
                    uint32_t b0 = bp[0], b1v = bp[4];
                    mma16(acc[0][nt], af[0][0], af[0][1], af[0][2], af[0][3], b0, b1v);
                    mma16(acc[1][nt], af[1][0], af[1][1], af[1][2], af[1][3], b0, b1v);
                }
            }
            // In-place h update: rows shared between the two n-warps -> all reads first.
            __syncthreads();
            #pragma unroll
            for (int t = 0; t < 2; ++t) {
                int rr = (t == 0) ? rA0 : rA1;
                #pragma unroll
                for (int nt = 0; nt < 5; ++nt) {
                    int c = nbase + nt * 8 + 2 * tig;
                    float v0 = fmaxf(acc[t][nt][0] + sbias[640 + l * F + c],     0.f);
                    float v1 = fmaxf(acc[t][nt][1] + sbias[640 + l * F + c + 1], 0.f);
                    float v2 = fmaxf(acc[t][nt][2] + sbias[640 + l * F + c],     0.f);
                    float v3 = fmaxf(acc[t][nt][3] + sbias[640 + l * F + c + 1], 0.f);
                    Xw[rr * XSW + nbw + nt * 4 + tig]       = packh2(v0, v1);
                    Xw[(rr + 8) * XSW + nbw + nt * 4 + tig] = packh2(v2, v3);
                }
            }
        } else {
            // ---------- Layer 4, full K, game g (writes only to global) ----------
            int g = gLo + (s - nG - 2);
            const int nT4 = (nw == 0) ? 2 : 1;  // nw0 -> nt{0,1}, nw1 -> nt{2}
            #pragma unroll
            for (int t = 0; t < 2; ++t)
                #pragma unroll
                for (int i = 0; i < 2; ++i)
                    #pragma unroll
                    for (int q2 = 0; q2 < 4; ++q2) acc[t][i][q2] = 0.f;
            #pragma unroll
            for (int ks = 0; ks < 5; ++ks) {
                int kx = ks * 8;
                uint32_t af[2][4];
                af[0][0] = Xw[rA0 * XSW + kx + tig];
                af[0][1] = Xw[(rA0 + 8) * XSW + kx + tig];
                af[0][2] = Xw[rA0 * XSW + kx + 4 + tig];
                af[0][3] = Xw[(rA0 + 8) * XSW + kx + 4 + tig];
                af[1][0] = Xw[rA1 * XSW + kx + tig];
                af[1][1] = Xw[(rA1 + 8) * XSW + kx + tig];
                af[1][2] = Xw[rA1 * XSW + kx + 4 + tig];
                af[1][3] = Xw[(rA1 + 8) * XSW + kx + 4 + tig];
                #pragma unroll
                for (int i = 0; i < 2; ++i) {
                    if (i < nT4) {
                        int ntG = nw * 2 + i;
                        // B rows 18..23 are zero-padded in the image
                        const uint32_t* bp = SWw + (ntG * 8 + gid) * WS + kx + tig;
                        uint32_t b0 = bp[0], b1v = bp[4];
                        mma16(acc[0][i], af[0][0], af[0][1], af[0][2], af[0][3], b0, b1v);
                        mma16(acc[1][i], af[1][0], af[1][1], af[1][2], af[1][3], b0, b1v);
                    }
                }
            }
            #pragma unroll
            for (int i = 0; i < 2; ++i) {
                if (i < nT4) {
                    int ntG = nw * 2 + i;
                    int c = ntG * 8 + 2 * tig;
                    if (c < A) {  // c even, A even -> c+1 < A too
                        float bb0 = sbias[800 + g * A + c];
                        float bb1 = sbias[800 + g * A + c + 1];
                        #pragma unroll
                        for (int t = 0; t < 2; ++t) {
                            int rr = (t == 0) ? rA0 : rA1;
                            if (mg[t][0] == g) {
                                float2 v = make_float2(acc[t][i][0] + bb0, acc[t][i][1] + bb1);
                                *(float2*)(out + (size_t)(mBase + rr) * A + c) = v;
                            }
                            if (mg[t][1] == g) {
                                float2 v = make_float2(acc[t][i][2] + bb0, acc[t][i][3] + bb1);
                                *(float2*)(out + (size_t)(mBase + rr + 8) * A + c) = v;
                            }
                        }
                    }
                }
            }
        }

        if (s + 2 < nStages) issue_stage(s + 2, gLo, nG, slbase, tid);
        CPA_COMMIT();  // ALWAYS commit (empty tail groups keep wait_group counts aligned)
    }
}

extern "C" void kernel_launch(void* const* d_in, const int* in_sizes, int n_in,
                              void* d_out, int out_size) {
    const float* state = (const float*)d_in[0];
    const int*   idx   = (const int*)d_in[1];
    const float* W1    = (const float*)d_in[2];
    const float* b1    = (const float*)d_in[3];
    const float* W2    = (const float*)d_in[4];
    const float* b2    = (const float*)d_in[5];
    const float* W3    = (const float*)d_in[6];
    const float* b3    = (const float*)d_in[7];
    const float* W4    = (const float*)d_in[8];
    const float* b4    = (const float*)d_in[9];
    float* out = (float*)d_out;

    const int B = in_sizes[1];

    int prepN = G * F * W1SW;  // 43520 (largest image)
    prep_kernel<<<(prepN + 255) / 256, 256>>>(W1, W2, W3, W4);

    cudaFuncSetAttribute(fused_kernel, cudaFuncAttributeMaxDynamicSharedMemorySize, SMEM_BYTES);
    int grid = (B + BM - 1) / BM;
    fused_kernel<<<grid, THREADS, SMEM_BYTES>>>(state, idx, b1, b2, b3, b4, out, B);
}

// round 17
// speedup vs baseline: 1.7252x; 1.7252x over previous
#include <cuda_runtime.h>
#include <cuda_fp16.h>
#include <cstdint>

#define DI __device__ __forceinline__

constexpr int D = 128, G = 8, F = 80, A = 18;
constexpr int BM = 256, THREADS = 256;   // 256 rows per CTA; warp = 4 m16-tiles x 5 n-tiles

// strides in 32-bit WORDS (each word = 2 fp16)
constexpr int XSW  = 68;  // X row stride: 68 % 32 == 4 -> conflict-free LDS.32 frags
constexpr int W1S  = 20;  // W1-quarter slot stride: 20g+t distinct mod 32
constexpr int WS   = 44;  // W2/3/4 slot stride: 44 % 32 == 12 -> distinct
constexpr int SLOTW = 80 * WS;              // 3520 words per slot (max stage)
constexpr int OFF_X  = 0;                   // 256*68 = 17408 words
constexpr int OFF_SL = BM * XSW;            // 3 rotating slots
constexpr int OFF_SB = OFF_SL + 3 * SLOTW;  // b2(80)+b3(80) fp32
constexpr int SMEM_WORDS = OFF_SB + 2 * F;  // 28128
constexpr int SMEM_BYTES = SMEM_WORDS * 4;  // 112512 B -> 2 CTAs/SM (2x114688 <= 233472)

// fp16-packed weight images (layout == staged layout; one uint32 = 2 halves)
__device__ __align__(16) uint32_t g_W1h[G * 4 * F * W1S];  // [g][q][n][20w]
__device__ __align__(16) uint32_t g_W23h[2 * F * WS];      // [l][n][44w]
__device__ __align__(16) uint32_t g_W4h[G * 24 * WS];      // [g][n<24][44w]

DI uint32_t packh2(float a, float b) {
    __half2 h = __floats2half2_rn(a, b);
    return *(uint32_t*)&h;
}

DI void mma16(float* c, uint32_t a0, uint32_t a1, uint32_t a2, uint32_t a3,
              uint32_t b0, uint32_t b1) {
    asm("mma.sync.aligned.m16n8k16.row.col.f32.f16.f16.f32 "
        "{%0,%1,%2,%3}, {%4,%5,%6,%7}, {%8,%9}, {%0,%1,%2,%3};"
        : "+f"(c[0]), "+f"(c[1]), "+f"(c[2]), "+f"(c[3])
        : "r"(a0), "r"(a1), "r"(a2), "r"(a3), "r"(b0), "r"(b1));
}

DI void cpa16(uint32_t dst, const void* src) {
    asm volatile("cp.async.cg.shared.global [%0], [%1], 16;" :: "r"(dst), "l"(src));
}
#define CPA_COMMIT() asm volatile("cp.async.commit_group;" ::: "memory")
#define CPA_WAIT1()  asm volatile("cp.async.wait_group 1;" ::: "memory")

__global__ void prep_kernel(const float* __restrict__ W1, const float* __restrict__ W2,
                            const float* __restrict__ W3, const float* __restrict__ W4) {
    int i = blockIdx.x * blockDim.x + threadIdx.x;
    if (i < G * 4 * F * W1S) {  // i = ((g*4+q)*F + n)*20 + w
        int w = i % W1S; int r = i / W1S;
        int n = r % F; r /= F;
        int q = r & 3; int g = r >> 2;
        uint32_t v = 0;
        if (w < 16) {
            const float* p = W1 + (size_t)(g * F + n) * D + q * 32 + 2 * w;
            v = packh2(p[0], p[1]);
        }
        g_W1h[i] = v;
    }
    if (i < 2 * F * WS) {  // i = (l*F + n)*44 + w
        int w = i % WS; int r = i / WS;
        int n = r % F; int l = r / F;
        uint32_t v = 0;
        if (w < 40) {
            const float* W = l ? W3 : W2;
            v = packh2(W[n * F + 2 * w], W[n * F + 2 * w + 1]);
        }
        g_W23h[i] = v;
    }
    if (i < G * 24 * WS) {  // i = (g*24 + n)*44 + w
        int w = i % WS; int r = i / WS;
        int n = r % 24; int g = r / 24;
        uint32_t v = 0;
        if (n < A && w < 40) {
            const float* p = W4 + (size_t)(g * A + n) * F + 2 * w;
            v = packh2(p[0], p[1]);
        }
        g_W4h[i] = v;
    }
}

// prefetch stage s into slot s%3 (linear copies of preformatted images)
DI void issue_stage(int s, int gLo, int nG, uint32_t slbase, int tid) {
    uint32_t dst = slbase + (uint32_t)(s % 3) * (SLOTW * 4);
    const uint32_t* src; int nch;
    if (s < 4 * nG) {                       // W1 quarter: 80*20 w = 400 f4
        int g = gLo + (s >> 2), q = s & 3;
        src = g_W1h + (size_t)(g * 4 + q) * F * W1S; nch = 400;
    } else {
        int t = s - 4 * nG;
        if (t < 2) { src = g_W23h + (size_t)t * F * WS; nch = 880; }   // 80*44 w
        else       { src = g_W4h + (size_t)(gLo + t - 2) * 24 * WS; nch = 264; }
    }
    for (int c = tid; c < nch; c += THREADS)
        cpa16(dst + c * 16, src + c * 4);
}

__global__ __launch_bounds__(THREADS, 2)
void fused_kernel(const float* __restrict__ state, const int* __restrict__ idx,
                  const float* __restrict__ b1, const float* __restrict__ b2,
                  const float* __restrict__ b3, const float* __restrict__ b4,
                  float* __restrict__ out, int nTotal)
{
    extern __shared__ float sm[];
    uint32_t* Xw = (uint32_t*)sm;         // fp16 state (64 w/row), then h (40 w/row) in place
    float*    sb = sm + OFF_SB;           // [0..79]=b2, [80..159]=b3

    uint32_t su;
    asm("{ .reg .u64 t; cvta.to.shared.u64 t, %1; cvt.u32.u64 %0, t; }"
        : "=r"(su) : "l"(sm));
    const uint32_t slbase = su + OFF_SL * 4;

    const int tid  = threadIdx.x;
    const int lane = tid & 31;
    const int wid  = tid >> 5;
    const int gid  = lane >> 2;
    const int tig  = lane & 3;

    // 4 m-warps x 2 n-warps; each warp: 4 m16 tiles x 5 n-tiles (its 40 cols)
    const int mw = wid & 3;
    const int nw = wid >> 2;
    const int nbase = nw * 40;            // column base (half units)
    const int nbw   = nw * 20;            // column base (word units)
    int rA[4];
    #pragma unroll
    for (int t = 0; t < 4; ++t) rA[t] = mw * 64 + t * 16 + gid;

    const int mBase  = blockIdx.x * BM;
    const int nValid = min(BM, nTotal - mBase);

    const int gLo = __ldg(&idx[mBase]);
    const int gHi = __ldg(&idx[mBase + nValid - 1]);
    const int nG = gHi - gLo + 1;
    const int nStages = 5 * nG + 2;  // 4*nG (W1 quarters) + 2 (W2,W3) + nG (W4)

    int mg[4][2];
    #pragma unroll
    for (int t = 0; t < 4; ++t) {
        mg[t][0] = (rA[t]     < nValid) ? __ldg(&idx[mBase + rA[t]])     : -1;
        mg[t][1] = (rA[t] + 8 < nValid) ? __ldg(&idx[mBase + rA[t] + 8]) : -1;
    }

    if (tid < 2 * F) sb[tid] = (tid < F) ? b2[tid] : b3[tid - F];

    // ---- prologue: stage state (fp32 -> fp16, coalesced) + weight stages 0,1 ----
    {
        const float4* s4 = (const float4*)state;
        for (int c = tid; c < BM * 32; c += THREADS) {
            int m = c >> 5, c4 = c & 31;
            int row = min(mBase + m, nTotal - 1);
            float4 v = s4[(size_t)row * 32 + c4];
            Xw[m * XSW + 2 * c4]     = packh2(v.x, v.y);
            Xw[m * XSW + 2 * c4 + 1] = packh2(v.z, v.w);
        }
    }
    issue_stage(0, gLo, nG, slbase, tid); CPA_COMMIT();
    issue_stage(1, gLo, nG, slbase, tid); CPA_COMMIT();

    float acc[4][5][4];

    for (int s = 0; s < nStages; ++s) {
        CPA_WAIT1();
        __syncthreads();  // stage s weights (and, at s=0, the state tile) visible to all
        const uint32_t* SWw = (const uint32_t*)sm + OFF_SL + (s % 3) * SLOTW;

        if (s < 4 * nG) {
            // ---------- Layer 1, quarter q of game g (2 k16-steps) ----------
            int g = gLo + (s >> 2), q = s & 3;
            if (q == 0) {
                #pragma unroll
                for (int t = 0; t < 4; ++t)
                    #pragma unroll
                    for (int nt = 0; nt < 5; ++nt)
                        #pragma unroll
                        for (int i = 0; i < 4; ++i) acc[t][nt][i] = 0.f;
            }
            #pragma unroll
            for (int ks = 0; ks < 2; ++ks) {
                int kx = q * 16 + ks * 8;   // word offset into state
                uint32_t af[4][4];
                #pragma unroll
                for (int t = 0; t < 4; ++t) {
                    af[t][0] = Xw[rA[t] * XSW + kx + tig];
                    af[t][1] = Xw[(rA[t] + 8) * XSW + kx + tig];
                    af[t][2] = Xw[rA[t] * XSW + kx + 4 + tig];
                    af[t][3] = Xw[(rA[t] + 8) * XSW + kx + 4 + tig];
                }
                #pragma unroll
                for (int nt = 0; nt < 5; ++nt) {
                    const uint32_t* bp = SWw + (nbase + nt * 8 + gid) * W1S + ks * 8 + tig;
                    uint32_t b0 = bp[0], b1v = bp[4];
                    #pragma unroll
                    for (int t = 0; t < 4; ++t)
                        mma16(acc[t][nt], af[t][0], af[t][1], af[t][2], af[t][3], b0, b1v);
                }
            }
            if (q == 3) {
                // masked epilogue -> h1 words 0..39; q=3 MMA reads words 48..63: disjoint.
                #pragma unroll
                for (int t = 0; t < 4; ++t) {
                    #pragma unroll
                    for (int hf = 0; hf < 2; ++hf) {
                        if (mg[t][hf] == g) {
                            int row = rA[t] + hf * 8;
                            #pragma unroll
                            for (int nt = 0; nt < 5; ++nt) {
                                int c = nbase + nt * 8 + 2 * tig;
                                float v0 = fmaxf(acc[t][nt][2 * hf]     + __ldg(&b1[g * F + c]),     0.f);
                                float v1 = fmaxf(acc[t][nt][2 * hf + 1] + __ldg(&b1[g * F + c + 1]), 0.f);
                                Xw[row * XSW + nbw + nt * 4 + tig] = packh2(v0, v1);
                            }
                        }
                    }
                }
            }
        } else if (s - 4 * nG < 2) {
            // ---------- Layer 2 or 3, full K (5 k16-steps) ----------
            int l = s - 4 * nG;
            #pragma unroll
            for (int t = 0; t < 4; ++t)
                #pragma unroll
                for (int nt = 0; nt < 5; ++nt)
                    #pragma unroll
                    for (int i = 0; i < 4; ++i) acc[t][nt][i] = 0.f;
            #pragma unroll
            for (int ks = 0; ks < 5; ++ks) {
                int kx = ks * 8;
                uint32_t af[4][4];
                #pragma unroll
                for (int t = 0; t < 4; ++t) {
                    af[t][0] = Xw[rA[t] * XSW + kx + tig];
                    af[t][1] = Xw[(rA[t] + 8) * XSW + kx + tig];
                    af[t][2] = Xw[rA[t] * XSW + kx + 4 + tig];
                    af[t][3] = Xw[(rA[t] + 8) * XSW + kx + 4 + tig];
                }
                #pragma unroll
                for (int nt = 0; nt < 5; ++nt) {
                    const uint32_t* bp = SWw + (nbase + nt * 8 + gid) * WS + kx + tig;
                    uint32_t b0 = bp[0], b1v = bp[4];
                    #pragma unroll
                    for (int t = 0; t < 4; ++t)
                        mma16(acc[t][nt], af[t][0], af[t][1], af[t][2], af[t][3], b0, b1v);
                }
            }
            // In-place h update: rows shared between the two n-warps -> all reads first.
            __syncthreads();
            #pragma unroll
            for (int t = 0; t < 4; ++t) {
                #pragma unroll
                for (int nt = 0; nt < 5; ++nt) {
                    int c = nbase + nt * 8 + 2 * tig;
                    float v0 = fmaxf(acc[t][nt][0] + sb[l * F + c],     0.f);
                    float v1 = fmaxf(acc[t][nt][1] + sb[l * F + c + 1], 0.f);
                    float v2 = fmaxf(acc[t][nt][2] + sb[l * F + c],     0.f);
                    float v3 = fmaxf(acc[t][nt][3] + sb[l * F + c + 1], 0.f);
                    Xw[rA[t] * XSW + nbw + nt * 4 + tig]       = packh2(v0, v1);
                    Xw[(rA[t] + 8) * XSW + nbw + nt * 4 + tig] = packh2(v2, v3);
                }
            }
        } else {
            // ---------- Layer 4, full K, game g (writes only to global) ----------
            int g = gLo + (s - 4 * nG - 2);
            const int nT4 = (nw == 0) ? 2 : 1;  // nw0 -> nt{0,1}, nw1 -> nt{2}
            #pragma unroll
            for (int t = 0; t < 4; ++t)
                #pragma unroll
                for (int i = 0; i < 2; ++i)
                    #pragma unroll
                    for (int q2 = 0; q2 < 4; ++q2) acc[t][i][q2] = 0.f;
            #pragma unroll
            for (int ks = 0; ks < 5; ++ks) {
                int kx = ks * 8;
                uint32_t af[4][4];
                #pragma unroll
                for (int t = 0; t < 4; ++t) {
                    af[t][0] = Xw[rA[t] * XSW + kx + tig];
                    af[t][1] = Xw[(rA[t] + 8) * XSW + kx + tig];
                    af[t][2] = Xw[rA[t] * XSW + kx + 4 + tig];
                    af[t][3] = Xw[(rA[t] + 8) * XSW + kx + 4 + tig];
                }
                #pragma unroll
                for (int i = 0; i < 2; ++i) {
                    if (i < nT4) {
                        int ntG = nw * 2 + i;
                        // B rows 18..23 are zero-padded in the image
                        const uint32_t* bp = SWw + (ntG * 8 + gid) * WS + kx + tig;
                        uint32_t b0 = bp[0], b1v = bp[4];
                        #pragma unroll
                        for (int t = 0; t < 4; ++t)
                            mma16(acc[t][i], af[t][0], af[t][1], af[t][2], af[t][3], b0, b1v);
                    }
                }
            }
            #pragma unroll
            for (int i = 0; i < 2; ++i) {
                if (i < nT4) {
                    int ntG = nw * 2 + i;
                    int c = ntG * 8 + 2 * tig;
                    if (c < A) {  // c even, A even -> c+1 < A too
                        float bb0 = __ldg(&b4[g * A + c]);
                        float bb1 = __ldg(&b4[g * A + c + 1]);
                        #pragma unroll
                        for (int t = 0; t < 4; ++t) {
                            if (mg[t][0] == g) {
                                float2 v = make_float2(acc[t][i][0] + bb0, acc[t][i][1] + bb1);
                                *(float2*)(out + (size_t)(mBase + rA[t]) * A + c) = v;
                            }
                            if (mg[t][1] == g) {
                                float2 v = make_float2(acc[t][i][2] + bb0, acc[t][i][3] + bb1);
                                *(float2*)(out + (size_t)(mBase + rA[t] + 8) * A + c) = v;
                            }
                        }
                    }
                }
            }
        }

        if (s + 2 < nStages) issue_stage(s + 2, gLo, nG, slbase, tid);
        CPA_COMMIT();  // ALWAYS commit (empty tail groups keep wait_group counts aligned)
    }
}

extern "C" void kernel_launch(void* const* d_in, const int* in_sizes, int n_in,
                              void* d_out, int out_size) {
    const float* state = (const float*)d_in[0];
    const int*   idx   = (const int*)d_in[1];
    const float* W1    = (const float*)d_in[2];
    const float* b1    = (const float*)d_in[3];
    const float* W2    = (const float*)d_in[4];
    const float* b2    = (const float*)d_in[5];
    const float* W3    = (const float*)d_in[6];
    const float* b3    = (const float*)d_in[7];
    const float* W4    = (const float*)d_in[8];
    const float* b4    = (const float*)d_in[9];
    float* out = (float*)d_out;

    const int B = in_sizes[1];

    int prepN = G * 4 * F * W1S;  // 51200 (largest image)
    prep_kernel<<<(prepN + 255) / 256, 256>>>(W1, W2, W3, W4);

    cudaFuncSetAttribute(fused_kernel, cudaFuncAttributeMaxDynamicSharedMemorySize, SMEM_BYTES);
    int grid = (B + BM - 1) / BM;
    fused_kernel<<<grid, THREADS, SMEM_BYTES>>>(state, idx, b1, b2, b3, b4, out, B);
}